// round 16
// baseline (speedup 1.0000x reference)
#include <cuda_runtime.h>
#include <cuda_fp16.h>
#include <cstdint>

// Two-kernel split through HBM-resident fp16 h (replaces fused chunk loop):
//   K1: h  = relu(X@W0 + b0)   M=196608 N=1024 K=192, CTA tile 128x128
//   K2: out= relu(h@W1 + b1)   M=196608 N=256  K=1024, CTA tile 64x256
// DRAM was at 5% in the fused kernel; spending ~800MB h traffic buys clean
// GEMMs: single-barrier K1, 1-sync/chunk ping-pong K2, 2 CTAs/SM each.
// Numerics identical to R13 (same fp16 roundings): rel_err ~4.2e-4.

#define K1D  192
#define HID  1024
#define EMB  256

#define AW 100    // k1 A/B row stride (words): 192 fp16 + pad, 100%32=4
#define HW 36     // k2 A/B row stride (words): 64 fp16 + pad, 36%32=4

// ---- k1 smem ----
#define SM1_A   0                     // 128*400 = 51200
#define SM1_B   51200                 // 128*400 = 51200
#define SM1_B0  102400                // 512
#define SM1_TOTAL 102912              // x2 CTAs = 205824 <= 228KB

// ---- k2 smem ----
#define SM2_A   0                     // 2 x 64*144  = 18432
#define SM2_B   18432                 // 2 x 256*144 = 73728
#define SM2_B1  92160                 // 1024
#define SM2_TOTAL 93184               // x2 CTAs = 186368

__device__ __align__(16) __half g_B1[HID * K1D];            // W0^T [n][k]
__device__ __align__(16) __half g_B2[EMB * HID];            // W1^T [n][k]
__device__ __align__(16) __half g_h[(size_t)196608 * 1024]; // h buffer (384MB)

__device__ __forceinline__ void cpa16(uint32_t dst, const void* src) {
    asm volatile("cp.async.cg.shared.global [%0], [%1], 16;" :: "r"(dst), "l"(src) : "memory");
}
#define CP_COMMIT() asm volatile("cp.async.commit_group;" ::: "memory")
#define CP_WAIT0()  asm volatile("cp.async.wait_group 0;" ::: "memory")

__device__ __forceinline__ uint32_t smem_u32(const void* p) {
    uint32_t a;
    asm("{ .reg .u64 t; cvta.to.shared.u64 t, %1; cvt.u32.u64 %0, t; }" : "=r"(a) : "l"(p));
    return a;
}
__device__ __forceinline__ void ldsm4(uint32_t& r0, uint32_t& r1, uint32_t& r2,
                                      uint32_t& r3, uint32_t addr)
{
    asm volatile("ldmatrix.sync.aligned.m8n8.x4.shared.b16 {%0,%1,%2,%3}, [%4];"
        : "=r"(r0), "=r"(r1), "=r"(r2), "=r"(r3) : "r"(addr));
}
__device__ __forceinline__ void mma16816(float* c,
    uint32_t a0, uint32_t a1, uint32_t a2, uint32_t a3, uint32_t b0, uint32_t b1)
{
    asm volatile("mma.sync.aligned.m16n8k16.row.col.f32.f16.f16.f32 "
        "{%0,%1,%2,%3}, {%4,%5,%6,%7}, {%8,%9}, {%0,%1,%2,%3};"
        : "+f"(c[0]), "+f"(c[1]), "+f"(c[2]), "+f"(c[3])
        : "r"(a0), "r"(a1), "r"(a2), "r"(a3), "r"(b0), "r"(b1));
}
__device__ __forceinline__ uint32_t pack2(float x, float y) {
    __half2 h = __halves2half2(__float2half_rn(x), __float2half_rn(y));
    return *(uint32_t*)&h;
}

// ---------------- weight prep: fp16, transposed to [n][k] ----------------
__global__ void prep_kernel(const float* __restrict__ W0, const float* __restrict__ W1) {
    int stride = gridDim.x * blockDim.x;
    int t0 = blockIdx.x * blockDim.x + threadIdx.x;
    for (int i = t0; i < HID * K1D; i += stride) {
        int n = i / K1D, k = i % K1D;
        g_B1[n * K1D + k] = __float2half_rn(W0[k * HID + n]);
    }
    for (int i = t0; i < EMB * HID; i += stride) {
        int n = i / HID, k = i % HID;
        g_B2[n * HID + k] = __float2half_rn(W1[k * EMB + n]);
    }
}

// ================= K1: h = relu(X @ W0 + b0), 128x128 tile =================
__global__ void __launch_bounds__(256, 2)
k1_kernel(const float* __restrict__ x, const float* __restrict__ b0)
{
    extern __shared__ char smem[];
    const uint32_t sb = smem_u32(smem);
    const int tid  = threadIdx.x;
    const int lane = tid & 31;
    const int w    = tid >> 5;
    const int r    = lane >> 2;
    const int q    = lane & 3;
    const int m0   = (w >> 1) * 32;     // 4 m-groups
    const int n0   = (w & 1) * 64;      // 2 n-groups

    const int slice = blockIdx.x >> 3;  // 1536 slices
    const int nt    = blockIdx.x & 7;   // 8 n-tiles of 128

    uint32_t* asw = (uint32_t*)smem;
    float*    b0s = (float*)(smem + SM1_B0);

    // B tile: W0^T rows nt*128..+127, all 192 k (cp.async)
    {
        const __half* base = g_B1 + (size_t)(nt * 128) * K1D;
        #pragma unroll
        for (int i = tid; i < 3072; i += 256) {       // 128 rows x 24 x 16B
            int n = i / 24, u = i % 24;
            cpa16(sb + SM1_B + n * 400 + u * 16, base + n * K1D + u * 8);
        }
        CP_COMMIT();
    }
    // A tile: x slice [3ch][128tok][64bin] -> [128 rows][192] fp16
    {
        const float2* x2 = (const float2*)x + (size_t)slice * 12288;
        #pragma unroll 4
        for (int i = tid; i < 12288; i += 256) {
            int m = i / 96, u = i % 96, ch = u >> 5, bp = u & 31;
            float2 v = x2[ch * 4096 + m * 32 + bp];
            asw[m * AW + ch * 32 + bp] = pack2(v.x, v.y);
        }
        if (tid < 128) b0s[tid] = b0[nt * 128 + tid];
    }
    CP_WAIT0();
    __syncthreads();

    const uint32_t baseA = sb
        + (uint32_t)(((m0 + (lane & 15)) * AW + ((lane >> 4) << 2)) * 4);
    const uint32_t baseB = sb + SM1_B
        + (uint32_t)(((n0 + (lane & 7) + ((lane >> 4) << 3)) * AW
                      + (((lane >> 3) & 1) << 2)) * 4);

    float acc[16][4];
    #pragma unroll
    for (int j = 0; j < 16; j++)
        #pragma unroll
        for (int e = 0; e < 4; e++) acc[j][e] = 0.0f;

    #pragma unroll 4
    for (int kk = 0; kk < 12; kk++) {
        const uint32_t ko = kk * 32;
        uint32_t a[2][4];
        ldsm4(a[0][0], a[0][1], a[0][2], a[0][3], baseA + ko);          // rows m0..+15
        ldsm4(a[1][0], a[1][1], a[1][2], a[1][3], baseA + 6400 + ko);   // rows +16..31
        #pragma unroll
        for (int jp = 0; jp < 4; jp++) {
            uint32_t c0, c1_, c2, c3;
            ldsm4(c0, c1_, c2, c3, baseB + jp * 6400 + ko);             // n-tiles 2jp,2jp+1
            const int j0 = jp * 2;
            #pragma unroll
            for (int f = 0; f < 2; f++) {
                mma16816(acc[j0 * 2 + f],       a[f][0], a[f][1], a[f][2], a[f][3], c0, c1_);
                mma16816(acc[(j0 + 1) * 2 + f], a[f][0], a[f][1], a[f][2], a[f][3], c2, c3);
            }
        }
    }

    // epilogue: +b0, relu, fp16 -> g_h (row-major [196608][1024])
    uint32_t* gh = (uint32_t*)g_h;
    #pragma unroll
    for (int j = 0; j < 8; j++) {
        int n = n0 + j * 8 + q * 2;                   // local col in 128-tile
        float bb0 = b0s[n], bb1 = b0s[n + 1];
        #pragma unroll
        for (int f = 0; f < 2; f++) {
            const int row = slice * 128 + m0 + f * 16 + r;
            const size_t colw = (size_t)nt * 64 + (n >> 1);
            gh[(size_t)row * 512 + colw] =
                pack2(fmaxf(acc[j * 2 + f][0] + bb0, 0.f),
                      fmaxf(acc[j * 2 + f][1] + bb1, 0.f));
            gh[(size_t)(row + 8) * 512 + colw] =
                pack2(fmaxf(acc[j * 2 + f][2] + bb0, 0.f),
                      fmaxf(acc[j * 2 + f][3] + bb1, 0.f));
        }
    }
}

// ================= K2: out = relu(h @ W1 + b1), 64x256 tile =================
__device__ __forceinline__ void k2_load(uint32_t sb, int buf, size_t r0, int c, int tid) {
    // A: h rows r0..r0+63, k-slice c*64 (64 rows x 128B)
    const __half* ha = g_h + (size_t)c * 64;
    #pragma unroll
    for (int i = tid; i < 512; i += 256) {
        int n = i / 8, u = i % 8;
        cpa16(sb + SM2_A + buf * 9216 + n * 144 + u * 16,
              ha + (r0 + n) * 1024 + u * 8);
    }
    // B: W1^T all 256 rows, k-slice c*64
    const __half* hb = g_B2 + (size_t)c * 64;
    #pragma unroll
    for (int i = tid; i < 2048; i += 256) {
        int n = i / 8, u = i % 8;
        cpa16(sb + SM2_B + buf * 36864 + n * 144 + u * 16,
              hb + (size_t)n * 1024 + u * 8);
    }
    CP_COMMIT();
}

__global__ void __launch_bounds__(256, 2)
k2_kernel(const float* __restrict__ b1, float* __restrict__ out)
{
    extern __shared__ char smem[];
    const uint32_t sb = smem_u32(smem);
    const int tid  = threadIdx.x;
    const int lane = tid & 31;
    const int w    = tid >> 5;
    const int r    = lane >> 2;
    const int q    = lane & 3;
    const int m2   = (w >> 2) * 32;     // 2 m-groups
    const int n2   = (w & 3) * 64;      // 4 n-groups

    const size_t r0 = (size_t)blockIdx.x * 64;
    float* b1s = (float*)(smem + SM2_B1);

    k2_load(sb, 0, r0, 0, tid);
    if (tid < 256) b1s[tid] = b1[tid];

    float acc2[16][4];
    #pragma unroll
    for (int j = 0; j < 16; j++)
        #pragma unroll
        for (int e = 0; e < 4; e++) acc2[j][e] = 0.0f;

    for (int c = 0; c < 16; c++) {
        CP_WAIT0();                    // chunk c resident
        __syncthreads();               // also: all warps done reading buf (c-1)
        const int pb = c & 1;
        if (c < 15) k2_load(sb, pb ^ 1, r0, c + 1, tid);   // overlap with compute

        const uint32_t bA = sb + SM2_A + pb * 9216
            + (uint32_t)(((m2 + (lane & 15)) * HW + ((lane >> 4) << 2)) * 4);
        const uint32_t bB = sb + SM2_B + pb * 36864
            + (uint32_t)(((n2 + (lane & 7) + ((lane >> 4) << 3)) * HW
                          + (((lane >> 3) & 1) << 2)) * 4);

        #pragma unroll
        for (int kk = 0; kk < 4; kk++) {
            const uint32_t ko = kk * 32;
            uint32_t a[2][4];
            ldsm4(a[0][0], a[0][1], a[0][2], a[0][3], bA + ko);
            ldsm4(a[1][0], a[1][1], a[1][2], a[1][3], bA + 2304 + ko);
            #pragma unroll
            for (int jp = 0; jp < 4; jp++) {
                uint32_t c0, c1_, c2, c3;
                ldsm4(c0, c1_, c2, c3, bB + jp * 2304 + ko);
                const int j0 = jp * 2;
                #pragma unroll
                for (int f = 0; f < 2; f++) {
                    mma16816(acc2[j0 * 2 + f],       a[f][0], a[f][1], a[f][2], a[f][3], c0, c1_);
                    mma16816(acc2[(j0 + 1) * 2 + f], a[f][0], a[f][1], a[f][2], a[f][3], c2, c3);
                }
            }
        }
    }

    // epilogue: +b1, relu, store fp32
    #pragma unroll
    for (int j = 0; j < 8; j++) {
        int n = n2 + j * 8 + q * 2;
        float bb0 = b1s[n], bb1 = b1s[n + 1];
        #pragma unroll
        for (int f = 0; f < 2; f++) {
            const size_t rowg = r0 + m2 + f * 16 + r;
            float2 o0, o1;
            o0.x = fmaxf(acc2[j * 2 + f][0] + bb0, 0.f);
            o0.y = fmaxf(acc2[j * 2 + f][1] + bb1, 0.f);
            o1.x = fmaxf(acc2[j * 2 + f][2] + bb0, 0.f);
            o1.y = fmaxf(acc2[j * 2 + f][3] + bb1, 0.f);
            *(float2*)(out + rowg * 256 + n)       = o0;
            *(float2*)(out + (rowg + 8) * 256 + n) = o1;
        }
    }
}

extern "C" void kernel_launch(void* const* d_in, const int* in_sizes, int n_in,
                              void* d_out, int out_size)
{
    const float* x  = (const float*)d_in[0];
    const float* W0 = (const float*)d_in[1];
    const float* b0 = (const float*)d_in[2];
    const float* W1 = (const float*)d_in[3];
    const float* b1 = (const float*)d_in[4];
    float* out = (float*)d_out;

    static bool configured = false;
    if (!configured) {
        cudaFuncSetAttribute(k1_kernel,
                             cudaFuncAttributeMaxDynamicSharedMemorySize, SM1_TOTAL);
        cudaFuncSetAttribute(k2_kernel,
                             cudaFuncAttributeMaxDynamicSharedMemorySize, SM2_TOTAL);
        configured = true;
    }
    prep_kernel<<<256, 256>>>(W0, W1);
    k1_kernel<<<12288, 256, SM1_TOTAL>>>(x, b0);     // 1536 slices x 8 n-tiles
    k2_kernel<<<3072, 256, SM2_TOTAL>>>(b1, out);    // 196608/64 row-tiles
}